// round 2
// baseline (speedup 1.0000x reference)
#include <cuda_runtime.h>
#include <cstdint>

#define THREADS 512
#define ETILE   128
#define SA      68      // padded stride for 64-wide tiles (bank-conflict-free fragments)
#define SW2     196     // padded stride for W_mlp (192-wide)
#define LN_EPS  1e-5f

// shared-memory float offsets
#define OFF_EDGE 0                    // 128*68 = 8704 floats (aliased as "pre" after GEMM1)
#define OFF_E    8704                 // e tile
#define OFF_HEAD 17408
#define OFF_TAIL 26112
#define OFF_W1   34816                // 64*68
#define OFF_W2   39168                // 64*196
#define OFF_WAL  51712                // 192
#define OFF_BI   51904                // 64
#define OFF_BM   51968                // 64
#define OFF_BA   52032                // 1
#define SMEM_FLOATS 52036
#define SMEM_BYTES  (SMEM_FLOATS * 4)

// edges dtype flag: 1 if the edges buffer is genuinely int64, 0 if int32.
// (JAX with default x64-disabled silently makes "int64" arrays int32.)
__device__ int g_edges_is_i64;

__global__ void probe_edges_dtype(const long long* __restrict__ e64) {
    if (threadIdx.x == 0 && blockIdx.x == 0) {
        int ok = 1;
        #pragma unroll 8
        for (int i = 0; i < 64; ++i) {
            long long v = e64[i];
            if (v < 0 || v >= (1LL << 31)) ok = 0;   // int32 data misread as i64 -> huge
        }
        g_edges_is_i64 = ok;
    }
}

// round fp32 -> tf32 (rna) so HW truncation inside mma is exact (avoids biased error)
__device__ __forceinline__ uint32_t tf32r(float x) {
    uint32_t u;
    asm("cvt.rna.tf32.f32 %0, %1;" : "=r"(u) : "f"(x));
    return u;
}
__device__ __forceinline__ float tf32f(float x) { return __uint_as_float(tf32r(x)); }

__device__ __forceinline__ void mma_tf32(float c[4], const uint32_t a[4], const uint32_t b[2]) {
    asm volatile(
        "mma.sync.aligned.m16n8k8.row.col.f32.tf32.tf32.f32 "
        "{%0,%1,%2,%3}, {%4,%5,%6,%7}, {%8,%9}, {%0,%1,%2,%3};\n"
        : "+f"(c[0]), "+f"(c[1]), "+f"(c[2]), "+f"(c[3])
        : "r"(a[0]), "r"(a[1]), "r"(a[2]), "r"(a[3]), "r"(b[0]), "r"(b[1]));
}

__global__ void __launch_bounds__(THREADS, 1)
edge_update_kernel(const float* __restrict__ node_fts,
                   const float* __restrict__ edge_fts,
                   const void* __restrict__ edges_raw,
                   const float* __restrict__ W_init,
                   const float* __restrict__ b_init,
                   const float* __restrict__ W_mlp,
                   const float* __restrict__ b_mlp,
                   const float* __restrict__ W_alpha,
                   const float* __restrict__ b_alpha,
                   float* __restrict__ out,
                   int n_edges)
{
    extern __shared__ float sm[];
    const int tid  = threadIdx.x;
    const int base = blockIdx.x * ETILE;
    const int rem  = min(ETILE, n_edges - base);
    const int is64 = g_edges_is_i64;
    const long long* __restrict__ e64 = (const long long*)edges_raw;
    const int*       __restrict__ e32 = (const int*)edges_raw;

    // ---------------- phase 1: stage tiles + weights (tf32-rounded) ----------------
    {
        const int rr  = tid >> 4;          // 32 rows per pass
        const int seg = (tid & 15) * 4;    // 16 threads * float4 per 64-float row
        #pragma unroll
        for (int it = 0; it < 4; ++it) {
            int r = rr + it * 32;
            float4 v = make_float4(0.f, 0.f, 0.f, 0.f);
            float4 h = v, t = v;
            if (r < rem) {
                size_t e = (size_t)(base + r);
                v = *(const float4*)(edge_fts + e * 64 + seg);
                int hidx, tidx;
                if (is64) {
                    hidx = (int)e64[e];
                    tidx = (int)e64[(size_t)n_edges + e];
                } else {
                    hidx = e32[e];
                    tidx = e32[(size_t)n_edges + e];
                }
                h = *(const float4*)(node_fts + (size_t)hidx * 64 + seg);
                t = *(const float4*)(node_fts + (size_t)tidx * 64 + seg);
            }
            float* pe = sm + OFF_EDGE + r * SA + seg;
            pe[0] = tf32f(v.x); pe[1] = tf32f(v.y); pe[2] = tf32f(v.z); pe[3] = tf32f(v.w);
            float* ph = sm + OFF_HEAD + r * SA + seg;
            ph[0] = tf32f(h.x); ph[1] = tf32f(h.y); ph[2] = tf32f(h.z); ph[3] = tf32f(h.w);
            float* pt = sm + OFF_TAIL + r * SA + seg;
            pt[0] = tf32f(t.x); pt[1] = tf32f(t.y); pt[2] = tf32f(t.z); pt[3] = tf32f(t.w);
        }
        // W_init: 64x64, stored [n][k]
        for (int i = tid; i < 64 * 16; i += THREADS) {
            int rw = i >> 4, sg = (i & 15) * 4;
            float4 v = *(const float4*)(W_init + rw * 64 + sg);
            float* p = sm + OFF_W1 + rw * SA + sg;
            p[0] = tf32f(v.x); p[1] = tf32f(v.y); p[2] = tf32f(v.z); p[3] = tf32f(v.w);
        }
        // W_mlp: 64x192, stored [n][k]
        for (int i = tid; i < 64 * 48; i += THREADS) {
            int rw = i / 48, sg = (i % 48) * 4;
            float4 v = *(const float4*)(W_mlp + rw * 192 + sg);
            float* p = sm + OFF_W2 + rw * SW2 + sg;
            p[0] = tf32f(v.x); p[1] = tf32f(v.y); p[2] = tf32f(v.z); p[3] = tf32f(v.w);
        }
        if (tid < 192) sm[OFF_WAL + tid] = W_alpha[tid];
        if (tid < 64)  sm[OFF_BI + tid] = b_init[tid];
        else if (tid < 128) sm[OFF_BM + tid - 64] = b_mlp[tid - 64];
        else if (tid == 128) sm[OFF_BA] = b_alpha[0];
    }
    __syncthreads();

    const int warp = tid >> 5;
    const int lane = tid & 31;
    const int g    = lane >> 2;
    const int t4   = lane & 3;
    const int wm   = warp >> 1;        // 8 M-slices of 16 rows
    const int wn   = warp & 1;         // 2 N-slices of 32 cols
    const int row0 = wm * 16 + g;
    const int row1 = row0 + 8;
    const int ncol = wn * 32;

    float acc[4][4];

    // ---------------- GEMM1: e = edge @ W_init^T ----------------
    #pragma unroll
    for (int i = 0; i < 4; i++)
        #pragma unroll
        for (int j = 0; j < 4; j++) acc[i][j] = 0.f;

    {
        const float* A1 = sm + OFF_EDGE;
        const float* B1 = sm + OFF_W1;
        #pragma unroll
        for (int ks = 0; ks < 8; ++ks) {
            const int k0 = ks * 8;
            uint32_t a[4];
            a[0] = __float_as_uint(A1[row0 * SA + k0 + t4]);
            a[1] = __float_as_uint(A1[row1 * SA + k0 + t4]);
            a[2] = __float_as_uint(A1[row0 * SA + k0 + t4 + 4]);
            a[3] = __float_as_uint(A1[row1 * SA + k0 + t4 + 4]);
            #pragma unroll
            for (int nt = 0; nt < 4; ++nt) {
                const int n0 = ncol + nt * 8;
                uint32_t b[2];
                b[0] = __float_as_uint(B1[(n0 + g) * SA + k0 + t4]);
                b[1] = __float_as_uint(B1[(n0 + g) * SA + k0 + t4 + 4]);
                mma_tf32(acc[nt], a, b);
            }
        }
    }
    // write e (+b_init), tf32-rounded so GEMM2 consumes exact tf32
    #pragma unroll
    for (int nt = 0; nt < 4; ++nt) {
        const int c0 = ncol + nt * 8 + 2 * t4;
        const float b0 = sm[OFF_BI + c0], b1 = sm[OFF_BI + c0 + 1];
        *(float2*)(sm + OFF_E + row0 * SA + c0) =
            make_float2(tf32f(acc[nt][0] + b0), tf32f(acc[nt][1] + b1));
        *(float2*)(sm + OFF_E + row1 * SA + c0) =
            make_float2(tf32f(acc[nt][2] + b0), tf32f(acc[nt][3] + b1));
    }
    __syncthreads();

    // ---------------- GEMM2: pre = [e|head|tail] @ W_mlp^T ----------------
    #pragma unroll
    for (int i = 0; i < 4; i++)
        #pragma unroll
        for (int j = 0; j < 4; j++) acc[i][j] = 0.f;

    {
        const float* B2 = sm + OFF_W2;
        #pragma unroll
        for (int ks = 0; ks < 24; ++ks) {
            const float* Ab = sm + ((ks < 8) ? OFF_E : (ks < 16) ? OFF_HEAD : OFF_TAIL);
            const int k0 = (ks & 7) * 8;
            const int kw = ks * 8;
            uint32_t a[4];
            a[0] = __float_as_uint(Ab[row0 * SA + k0 + t4]);
            a[1] = __float_as_uint(Ab[row1 * SA + k0 + t4]);
            a[2] = __float_as_uint(Ab[row0 * SA + k0 + t4 + 4]);
            a[3] = __float_as_uint(Ab[row1 * SA + k0 + t4 + 4]);
            #pragma unroll
            for (int nt = 0; nt < 4; ++nt) {
                const int n0 = ncol + nt * 8;
                uint32_t b[2];
                b[0] = __float_as_uint(B2[(n0 + g) * SW2 + kw + t4]);
                b[1] = __float_as_uint(B2[(n0 + g) * SW2 + kw + t4 + 4]);
                mma_tf32(acc[nt], a, b);
            }
        }
    }
    // write pre (alias of edge tile buffer; edge tile is dead after GEMM1)
    #pragma unroll
    for (int nt = 0; nt < 4; ++nt) {
        const int c0 = ncol + nt * 8 + 2 * t4;
        *(float2*)(sm + OFF_EDGE + row0 * SA + c0) = make_float2(acc[nt][0], acc[nt][1]);
        *(float2*)(sm + OFF_EDGE + row1 * SA + c0) = make_float2(acc[nt][2], acc[nt][3]);
    }
    __syncthreads();

    // ---------------- epilogue: alpha, tanh, LN, LN, store ----------------
    {
        const float balpha = sm[OFF_BA];
        const int c0 = lane, c1 = lane + 32;
        for (int rr = 0; rr < 8; ++rr) {
            const int r = warp * 8 + rr;
            const float* pre = sm + OFF_EDGE + r * SA;
            const float* er  = sm + OFF_E + r * SA;
            float p0 = tanhf(pre[c0] + sm[OFF_BM + c0]);
            float p1 = tanhf(pre[c1] + sm[OFF_BM + c1]);
            // alpha partial: combined[k] * W_alpha[k]
            float ap = 0.f;
            #pragma unroll
            for (int j = 0; j < 6; ++j) {
                const int k = lane + 32 * j;
                float cv = (k < 64) ? er[k]
                         : (k < 128) ? sm[OFF_HEAD + r * SA + k - 64]
                                     : sm[OFF_TAIL + r * SA + k - 128];
                ap += cv * sm[OFF_WAL + k];
            }
            float s1 = p0 + p1;
            float s2 = p0 * p0 + p1 * p1;
            #pragma unroll
            for (int off = 16; off; off >>= 1) {
                s1 += __shfl_xor_sync(0xffffffffu, s1, off);
                s2 += __shfl_xor_sync(0xffffffffu, s2, off);
                ap += __shfl_xor_sync(0xffffffffu, ap, off);
            }
            const float alpha = 1.f / (1.f + expf(-(ap + balpha)));
            const float mean  = s1 * (1.f / 64.f);
            const float var   = s2 * (1.f / 64.f) - mean * mean;
            const float rstd  = rsqrtf(var + LN_EPS) * alpha;
            float y0 = er[c0] + (p0 - mean) * rstd;
            float y1 = er[c1] + (p1 - mean) * rstd;
            float u1 = y0 + y1, u2 = y0 * y0 + y1 * y1;
            #pragma unroll
            for (int off = 16; off; off >>= 1) {
                u1 += __shfl_xor_sync(0xffffffffu, u1, off);
                u2 += __shfl_xor_sync(0xffffffffu, u2, off);
            }
            const float m2  = u1 * (1.f / 64.f);
            const float v2  = u2 * (1.f / 64.f) - m2 * m2;
            const float rs2 = rsqrtf(v2 + LN_EPS);
            if (r < rem) {
                const size_t o = (size_t)(base + r) * 64;
                out[o + c0] = (y0 - m2) * rs2;
                out[o + c1] = (y1 - m2) * rs2;
            }
        }
    }
}

extern "C" void kernel_launch(void* const* d_in, const int* in_sizes, int n_in,
                              void* d_out, int out_size)
{
    const float* node_fts = (const float*)d_in[0];
    const float* edge_fts = (const float*)d_in[1];
    const void*  edges    = d_in[2];
    const float* W_init   = (const float*)d_in[3];
    const float* b_init   = (const float*)d_in[4];
    const float* W_mlp    = (const float*)d_in[5];
    const float* b_mlp    = (const float*)d_in[6];
    const float* W_alpha  = (const float*)d_in[7];
    const float* b_alpha  = (const float*)d_in[8];
    float*       out      = (float*)d_out;

    const int n_edges = in_sizes[1] / 64;      // edge_fts elements / EDGE_IN_FTS
    const int grid    = (n_edges + ETILE - 1) / ETILE;

    cudaFuncSetAttribute(edge_update_kernel,
                         cudaFuncAttributeMaxDynamicSharedMemorySize, SMEM_BYTES);
    probe_edges_dtype<<<1, 32>>>((const long long*)edges);
    edge_update_kernel<<<grid, THREADS, SMEM_BYTES>>>(
        node_fts, edge_fts, edges, W_init, b_init,
        W_mlp, b_mlp, W_alpha, b_alpha, out, n_edges);
}